// round 1
// baseline (speedup 1.0000x reference)
#include <cuda_runtime.h>
#include <cuda_bf16.h>
#include <cstddef>
#include <math.h>

// ---------------- problem constants ----------------
#define T_  2048
#define H_  4096
#define HQ_ 32
#define HKV_ 8
#define D_  128
#define I_  14336

// ---------------- scratch (device globals; no allocation allowed) ----------------
__device__ float g_h   [T_ * H_];       // rmsnorm output (reused for both norms)
__device__ float g_q   [T_ * HQ_ * D_];
__device__ float g_k   [T_ * HKV_ * D_];
__device__ float g_v   [T_ * HKV_ * D_];
__device__ float g_attn[T_ * H_];       // attention output (pre o-proj)
__device__ float g_x1  [T_ * H_];       // x + attn @ w_o^T
__device__ float g_gate[T_ * (size_t)I_]; // silu(h @ w_gate^T)
__device__ float g_gu  [T_ * (size_t)I_]; // gate * up

// ---------------- RMSNorm ----------------
__global__ void __launch_bounds__(256) rmsnorm_kernel(
    const float* __restrict__ x, const float* __restrict__ w, float* __restrict__ out)
{
    const int row = blockIdx.x;
    const float4* xv = (const float4*)(x + (size_t)row * H_);
    const float4* wv = (const float4*)w;
    float4* ov = (float4*)(out + (size_t)row * H_);

    float4 buf[4];
    float ss = 0.f;
#pragma unroll
    for (int i = 0; i < 4; i++) {
        float4 v = xv[threadIdx.x + i * 256];
        buf[i] = v;
        ss += v.x * v.x + v.y * v.y + v.z * v.z + v.w * v.w;
    }
#pragma unroll
    for (int o = 16; o; o >>= 1) ss += __shfl_xor_sync(0xffffffffu, ss, o);

    __shared__ float wsum[8];
    __shared__ float s_inv;
    if ((threadIdx.x & 31) == 0) wsum[threadIdx.x >> 5] = ss;
    __syncthreads();
    if (threadIdx.x == 0) {
        float tot = 0.f;
#pragma unroll
        for (int i = 0; i < 8; i++) tot += wsum[i];
        s_inv = rsqrtf(tot * (1.f / (float)H_) + 1e-5f);
    }
    __syncthreads();
    const float inv = s_inv;
#pragma unroll
    for (int i = 0; i < 4; i++) {
        float4 v = buf[i];
        float4 ww = wv[threadIdx.x + i * 256];
        float4 o4;
        o4.x = v.x * inv * ww.x;
        o4.y = v.y * inv * ww.y;
        o4.z = v.z * inv * ww.z;
        o4.w = v.w * inv * ww.w;
        ov[threadIdx.x + i * 256] = o4;
    }
}

// ---------------- RoPE (in place) ----------------
__global__ void rope_kernel(float* __restrict__ x, const int* __restrict__ pos, int nheads)
{
    const int tt = blockIdx.x;
    const int h  = blockIdx.y;
    const int j  = threadIdx.x;   // 0..63
    const float p = (float)pos[tt];
    // THETA^(-j/64) ; log(500000)/64 to double precision
    const float invf = expf(-(float)j * 0.20503692777194262f);
    const float freq = p * invf;
    float s, c;
    sincosf(freq, &s, &c);
    float* base = x + ((size_t)tt * nheads + h) * D_ + j;
    const float x1v = base[0];
    const float x2v = base[64];
    base[0]  = x1v * c - x2v * s;
    base[64] = x2v * c + x1v * s;
}

// ---------------- GEMM: C[M,N] = A[M,K] * B[N,K]^T  (both row-major, K contiguous)
// MODE 0: store    MODE 1: C = Cin + acc    MODE 2: C = silu(acc)    MODE 3: C = Cin * acc
template <int MODE>
__global__ void __launch_bounds__(256, 2) gemm_nt_kernel(
    const float* __restrict__ A, const float* __restrict__ B,
    const float* __restrict__ Cin, float* __restrict__ C,
    int N, int K)
{
    __shared__ float As[2][8][128];
    __shared__ float Bs[2][8][128];

    const int t  = threadIdx.x;
    const int tx = t & 15;
    const int ty = t >> 4;
    const int lr = t >> 1;            // 0..127
    const int lc = (t & 1) * 4;       // 0 or 4

    const float* Ag = A + ((size_t)blockIdx.y * 128 + lr) * K + lc;
    const float* Bg = B + ((size_t)blockIdx.x * 128 + lr) * K + lc;

    float acc[8][8];
#pragma unroll
    for (int i = 0; i < 8; i++)
#pragma unroll
        for (int j = 0; j < 8; j++) acc[i][j] = 0.f;

    float4 a4 = *(const float4*)(Ag);
    float4 b4 = *(const float4*)(Bg);
    int buf = 0;

    for (int k0 = 0; k0 < K; k0 += 8) {
        As[buf][lc + 0][lr] = a4.x; As[buf][lc + 1][lr] = a4.y;
        As[buf][lc + 2][lr] = a4.z; As[buf][lc + 3][lr] = a4.w;
        Bs[buf][lc + 0][lr] = b4.x; Bs[buf][lc + 1][lr] = b4.y;
        Bs[buf][lc + 2][lr] = b4.z; Bs[buf][lc + 3][lr] = b4.w;
        __syncthreads();

        if (k0 + 8 < K) {
            a4 = *(const float4*)(Ag + k0 + 8);
            b4 = *(const float4*)(Bg + k0 + 8);
        }

#pragma unroll
        for (int k = 0; k < 8; k++) {
            float4 a0 = *(const float4*)&As[buf][k][ty * 8];
            float4 a1 = *(const float4*)&As[buf][k][ty * 8 + 4];
            float4 b0 = *(const float4*)&Bs[buf][k][tx * 8];
            float4 b1 = *(const float4*)&Bs[buf][k][tx * 8 + 4];
            float af[8] = {a0.x, a0.y, a0.z, a0.w, a1.x, a1.y, a1.z, a1.w};
            float bf[8] = {b0.x, b0.y, b0.z, b0.w, b1.x, b1.y, b1.z, b1.w};
#pragma unroll
            for (int i = 0; i < 8; i++)
#pragma unroll
                for (int j = 0; j < 8; j++) acc[i][j] += af[i] * bf[j];
        }
        buf ^= 1;
    }

    const int row0 = blockIdx.y * 128 + ty * 8;
    const int col0 = blockIdx.x * 128 + tx * 8;
#pragma unroll
    for (int i = 0; i < 8; i++) {
        float* crow = C + (size_t)(row0 + i) * N + col0;
        const float* cinrow = (MODE == 1 || MODE == 3)
                                  ? (Cin + (size_t)(row0 + i) * N + col0)
                                  : nullptr;
#pragma unroll
        for (int jj = 0; jj < 8; jj += 4) {
            float4 v = make_float4(acc[i][jj], acc[i][jj + 1], acc[i][jj + 2], acc[i][jj + 3]);
            if (MODE == 1) {
                float4 c0 = *(const float4*)(cinrow + jj);
                v.x += c0.x; v.y += c0.y; v.z += c0.z; v.w += c0.w;
            } else if (MODE == 2) {
                v.x = v.x / (1.f + expf(-v.x));
                v.y = v.y / (1.f + expf(-v.y));
                v.z = v.z / (1.f + expf(-v.z));
                v.w = v.w / (1.f + expf(-v.w));
            } else if (MODE == 3) {
                float4 c0 = *(const float4*)(cinrow + jj);
                v.x *= c0.x; v.y *= c0.y; v.z *= c0.z; v.w *= c0.w;
            }
            *(float4*)(crow + jj) = v;
        }
    }
}

// ---------------- causal flash attention (fp32) ----------------
// grid: (T/64, HQ), 256 threads. smem: Qs[64][133], Ks[64][133], Vs[64][128],
// Ps[64][64], red[64][16]
#define ATT_QS   (64 * 133)
#define ATT_SMEMF (ATT_QS * 2 + 64 * 128 + 64 * 64 + 64 * 16)
#define ATT_SMEMB (ATT_SMEMF * 4)

__global__ void __launch_bounds__(256) attn_kernel(
    const float* __restrict__ q, const float* __restrict__ kg,
    const float* __restrict__ vg, float* __restrict__ o)
{
    extern __shared__ float sm[];
    float* Qs  = sm;
    float* Ks  = Qs + ATT_QS;
    float* Vs  = Ks + ATT_QS;
    float* Ps  = Vs + 64 * 128;
    float* red = Ps + 64 * 64;

    const int qt   = blockIdx.x;
    const int head = blockIdx.y;
    const int kvh  = head >> 2;
    const int t    = threadIdx.x;
    const int tx   = t & 15;
    const int ty   = t >> 4;
    const int q0   = qt * 64;
    const float scale = 0.08838834764831845f;  // 1/sqrt(128)

    // load Q tile (64 x 128)
    {
        const int r  = t >> 2;
        const int cg = (t & 3) * 4;
        const float* src = q + ((size_t)(q0 + r)) * H_ + head * D_;
#pragma unroll
        for (int i = 0; i < 8; i++) {
            int c = cg + i * 16;
            float4 v4 = *(const float4*)(src + c);
            Qs[r * 133 + c + 0] = v4.x;
            Qs[r * 133 + c + 1] = v4.y;
            Qs[r * 133 + c + 2] = v4.z;
            Qs[r * 133 + c + 3] = v4.w;
        }
    }

    float m[4], l[4], acc[4][8];
#pragma unroll
    for (int i = 0; i < 4; i++) {
        m[i] = -1e30f;
        l[i] = 0.f;
#pragma unroll
        for (int j = 0; j < 8; j++) acc[i][j] = 0.f;
    }

    for (int kt = 0; kt <= qt; kt++) {
        __syncthreads();  // also guards Q load on first iteration / prev Ps-Ks-Vs use
        const int k0 = kt * 64;
        {
            const int r  = t >> 2;
            const int cg = (t & 3) * 4;
            const float* ksrc = kg + ((size_t)(k0 + r)) * (HKV_ * D_) + kvh * D_;
            const float* vsrc = vg + ((size_t)(k0 + r)) * (HKV_ * D_) + kvh * D_;
#pragma unroll
            for (int i = 0; i < 8; i++) {
                int c = cg + i * 16;
                float4 k4 = *(const float4*)(ksrc + c);
                Ks[r * 133 + c + 0] = k4.x;
                Ks[r * 133 + c + 1] = k4.y;
                Ks[r * 133 + c + 2] = k4.z;
                Ks[r * 133 + c + 3] = k4.w;
                float4 v4 = *(const float4*)(vsrc + c);
                *(float4*)&Vs[r * 128 + c] = v4;
            }
        }
        __syncthreads();

        // S = Q K^T
        float s[4][4];
#pragma unroll
        for (int i = 0; i < 4; i++)
#pragma unroll
            for (int j = 0; j < 4; j++) s[i][j] = 0.f;

#pragma unroll 8
        for (int k = 0; k < 128; k++) {
            float a[4], b[4];
#pragma unroll
            for (int i = 0; i < 4; i++) a[i] = Qs[(ty * 4 + i) * 133 + k];
#pragma unroll
            for (int j = 0; j < 4; j++) b[j] = Ks[(tx * 4 + j) * 133 + k];
#pragma unroll
            for (int i = 0; i < 4; i++)
#pragma unroll
                for (int j = 0; j < 4; j++) s[i][j] += a[i] * b[j];
        }

        // scale + causal mask + per-thread row max
        float rmax[4];
#pragma unroll
        for (int i = 0; i < 4; i++) {
            const int qi = q0 + ty * 4 + i;
            rmax[i] = -1e30f;
#pragma unroll
            for (int j = 0; j < 4; j++) {
                const int ki = k0 + tx * 4 + j;
                float v = s[i][j] * scale;
                if (ki > qi) v = -1e30f;
                s[i][j] = v;
                rmax[i] = fmaxf(rmax[i], v);
            }
        }
#pragma unroll
        for (int i = 0; i < 4; i++) red[(ty * 4 + i) * 16 + tx] = rmax[i];
        __syncthreads();

        float mnew[4], alpha[4];
#pragma unroll
        for (int i = 0; i < 4; i++) {
            float mx = m[i];
#pragma unroll
            for (int x2 = 0; x2 < 16; x2++) mx = fmaxf(mx, red[(ty * 4 + i) * 16 + x2]);
            mnew[i]  = mx;
            alpha[i] = expf(m[i] - mx);
            m[i]     = mx;
        }

        // p = exp(s - mnew), row sums
        float rsum[4];
#pragma unroll
        for (int i = 0; i < 4; i++) {
            rsum[i] = 0.f;
#pragma unroll
            for (int j = 0; j < 4; j++) {
                float p = expf(s[i][j] - mnew[i]);
                s[i][j] = p;
                rsum[i] += p;
            }
        }
        __syncthreads();  // everyone done reading red (max) before overwrite
#pragma unroll
        for (int i = 0; i < 4; i++) {
            red[(ty * 4 + i) * 16 + tx] = rsum[i];
#pragma unroll
            for (int j = 0; j < 4; j++)
                Ps[(ty * 4 + i) * 64 + tx * 4 + j] = s[i][j];
        }
        __syncthreads();
#pragma unroll
        for (int i = 0; i < 4; i++) {
            float sum = 0.f;
#pragma unroll
            for (int x2 = 0; x2 < 16; x2++) sum += red[(ty * 4 + i) * 16 + x2];
            l[i] = l[i] * alpha[i] + sum;
#pragma unroll
            for (int j = 0; j < 8; j++) acc[i][j] *= alpha[i];
        }

        // O += P V
#pragma unroll 4
        for (int k = 0; k < 64; k++) {
            float p4[4];
#pragma unroll
            for (int i = 0; i < 4; i++) p4[i] = Ps[(ty * 4 + i) * 64 + k];
            float4 v0 = *(const float4*)&Vs[k * 128 + tx * 8];
            float4 v1 = *(const float4*)&Vs[k * 128 + tx * 8 + 4];
#pragma unroll
            for (int i = 0; i < 4; i++) {
                acc[i][0] += p4[i] * v0.x;
                acc[i][1] += p4[i] * v0.y;
                acc[i][2] += p4[i] * v0.z;
                acc[i][3] += p4[i] * v0.w;
                acc[i][4] += p4[i] * v1.x;
                acc[i][5] += p4[i] * v1.y;
                acc[i][6] += p4[i] * v1.z;
                acc[i][7] += p4[i] * v1.w;
            }
        }
    }

    // epilogue: O / l  -> attn output laid out (T, HQ*D) = (T, H)
#pragma unroll
    for (int i = 0; i < 4; i++) {
        const float inv = 1.f / l[i];
        float* dst = o + (size_t)(q0 + ty * 4 + i) * H_ + head * D_ + tx * 8;
        float4 o0 = make_float4(acc[i][0] * inv, acc[i][1] * inv, acc[i][2] * inv, acc[i][3] * inv);
        float4 o1 = make_float4(acc[i][4] * inv, acc[i][5] * inv, acc[i][6] * inv, acc[i][7] * inv);
        *(float4*)(dst)     = o0;
        *(float4*)(dst + 4) = o1;
    }
}

// ---------------- launch ----------------
extern "C" void kernel_launch(void* const* d_in, const int* in_sizes, int n_in,
                              void* d_out, int out_size)
{
    (void)in_sizes; (void)n_in; (void)out_size;
    const float* x      = (const float*)d_in[0];
    const int*   pos    = (const int*)  d_in[1];
    const float* w_q    = (const float*)d_in[2];
    const float* w_k    = (const float*)d_in[3];
    const float* w_v    = (const float*)d_in[4];
    const float* w_o    = (const float*)d_in[5];
    const float* w_gate = (const float*)d_in[6];
    const float* w_up   = (const float*)d_in[7];
    const float* w_down = (const float*)d_in[8];
    const float* rms1   = (const float*)d_in[9];
    const float* rms2   = (const float*)d_in[10];
    float* out = (float*)d_out;

    float *h, *q, *k, *v, *attn, *x1, *gate, *gu;
    cudaGetSymbolAddress((void**)&h,    g_h);
    cudaGetSymbolAddress((void**)&q,    g_q);
    cudaGetSymbolAddress((void**)&k,    g_k);
    cudaGetSymbolAddress((void**)&v,    g_v);
    cudaGetSymbolAddress((void**)&attn, g_attn);
    cudaGetSymbolAddress((void**)&x1,   g_x1);
    cudaGetSymbolAddress((void**)&gate, g_gate);
    cudaGetSymbolAddress((void**)&gu,   g_gu);

    cudaFuncSetAttribute(attn_kernel, cudaFuncAttributeMaxDynamicSharedMemorySize, ATT_SMEMB);

    // 1. h = rmsnorm(x) * rms1
    rmsnorm_kernel<<<T_, 256>>>(x, rms1, h);
    // 2. q/k/v projections
    gemm_nt_kernel<0><<<dim3(H_ / 128, T_ / 128), 256>>>(h, w_q, nullptr, q, H_, H_);
    gemm_nt_kernel<0><<<dim3((HKV_ * D_) / 128, T_ / 128), 256>>>(h, w_k, nullptr, k, HKV_ * D_, H_);
    gemm_nt_kernel<0><<<dim3((HKV_ * D_) / 128, T_ / 128), 256>>>(h, w_v, nullptr, v, HKV_ * D_, H_);
    // 3. RoPE
    rope_kernel<<<dim3(T_, HQ_), 64>>>(q, pos, HQ_);
    rope_kernel<<<dim3(T_, HKV_), 64>>>(k, pos, HKV_);
    // 4. causal attention
    attn_kernel<<<dim3(T_ / 64, HQ_), 256, ATT_SMEMB>>>(q, k, v, attn);
    // 5. x1 = x + attn @ w_o^T
    gemm_nt_kernel<1><<<dim3(H_ / 128, T_ / 128), 256>>>(attn, w_o, x, x1, H_, H_);
    // 6. h = rmsnorm(x1) * rms2
    rmsnorm_kernel<<<T_, 256>>>(x1, rms2, h);
    // 7. gate = silu(h @ w_gate^T)
    gemm_nt_kernel<2><<<dim3(I_ / 128, T_ / 128), 256>>>(h, w_gate, nullptr, gate, I_, H_);
    // 8. gu = gate * (h @ w_up^T)
    gemm_nt_kernel<3><<<dim3(I_ / 128, T_ / 128), 256>>>(h, w_up, gate, gu, I_, H_);
    // 9. out = x1 + gu @ w_down^T
    gemm_nt_kernel<1><<<dim3(H_ / 128, T_ / 128), 256>>>(gu, w_down, x1, out, H_, I_);
}

// round 2
// speedup vs baseline: 2.8572x; 2.8572x over previous
#include <cuda_runtime.h>
#include <cuda_bf16.h>
#include <cstddef>
#include <cstdint>
#include <math.h>

// ---------------- problem constants ----------------
#define T_  2048
#define H_  4096
#define HQ_ 32
#define HKV_ 8
#define D_  128
#define I_  14336

// ---------------- scratch (device globals; no allocation allowed) ----------------
__device__ float g_h   [T_ * H_];
__device__ float g_q   [T_ * HQ_ * D_];
__device__ float g_k   [T_ * HKV_ * D_];
__device__ float g_v   [T_ * HKV_ * D_];
__device__ float g_attn[T_ * H_];
__device__ float g_x1  [T_ * H_];
__device__ float g_gate[T_ * (size_t)I_];
__device__ float g_gu  [T_ * (size_t)I_];

// ---------------- helpers ----------------
__device__ __forceinline__ uint32_t cvt_tf32(float x) {
    uint32_t r;
    asm("cvt.rna.tf32.f32 %0, %1;" : "=r"(r) : "f"(x));
    return r;
}

__device__ __forceinline__ void cp_async16(void* smem, const void* gmem) {
    uint32_t s = (uint32_t)__cvta_generic_to_shared(smem);
    asm volatile("cp.async.cg.shared.global [%0], [%1], 16;\n" :: "r"(s), "l"(gmem));
}
#define CP_COMMIT() asm volatile("cp.async.commit_group;\n" ::: "memory")
#define CP_WAIT0()  asm volatile("cp.async.wait_group 0;\n" ::: "memory")

__device__ __forceinline__ void mma_tf32(float* c,
    uint32_t a0, uint32_t a1, uint32_t a2, uint32_t a3,
    uint32_t b0, uint32_t b1)
{
    asm volatile(
        "mma.sync.aligned.m16n8k8.row.col.f32.tf32.tf32.f32 "
        "{%0,%1,%2,%3}, {%4,%5,%6,%7}, {%8,%9}, {%0,%1,%2,%3};"
        : "+f"(c[0]), "+f"(c[1]), "+f"(c[2]), "+f"(c[3])
        : "r"(a0), "r"(a1), "r"(a2), "r"(a3), "r"(b0), "r"(b1));
}

// ---------------- RMSNorm ----------------
__global__ void __launch_bounds__(256) rmsnorm_kernel(
    const float* __restrict__ x, const float* __restrict__ w, float* __restrict__ out)
{
    const int row = blockIdx.x;
    const float4* xv = (const float4*)(x + (size_t)row * H_);
    const float4* wv = (const float4*)w;
    float4* ov = (float4*)(out + (size_t)row * H_);

    float4 buf[4];
    float ss = 0.f;
#pragma unroll
    for (int i = 0; i < 4; i++) {
        float4 v = xv[threadIdx.x + i * 256];
        buf[i] = v;
        ss += v.x * v.x + v.y * v.y + v.z * v.z + v.w * v.w;
    }
#pragma unroll
    for (int o = 16; o; o >>= 1) ss += __shfl_xor_sync(0xffffffffu, ss, o);

    __shared__ float wsum[8];
    __shared__ float s_inv;
    if ((threadIdx.x & 31) == 0) wsum[threadIdx.x >> 5] = ss;
    __syncthreads();
    if (threadIdx.x == 0) {
        float tot = 0.f;
#pragma unroll
        for (int i = 0; i < 8; i++) tot += wsum[i];
        s_inv = rsqrtf(tot * (1.f / (float)H_) + 1e-5f);
    }
    __syncthreads();
    const float inv = s_inv;
#pragma unroll
    for (int i = 0; i < 4; i++) {
        float4 v = buf[i];
        float4 ww = wv[threadIdx.x + i * 256];
        float4 o4;
        o4.x = v.x * inv * ww.x;
        o4.y = v.y * inv * ww.y;
        o4.z = v.z * inv * ww.z;
        o4.w = v.w * inv * ww.w;
        ov[threadIdx.x + i * 256] = o4;
    }
}

// ---------------- RoPE (in place) ----------------
__global__ void rope_kernel(float* __restrict__ x, const int* __restrict__ pos, int nheads)
{
    const int tt = blockIdx.x;
    const int h  = blockIdx.y;
    const int j  = threadIdx.x;   // 0..63
    const float p = (float)pos[tt];
    const float invf = expf(-(float)j * 0.20503692777194262f);
    const float freq = p * invf;
    float s, c;
    sincosf(freq, &s, &c);
    float* base = x + ((size_t)tt * nheads + h) * D_ + j;
    const float x1v = base[0];
    const float x2v = base[64];
    base[0]  = x1v * c - x2v * s;
    base[64] = x2v * c + x1v * s;
}

// ---------------- TF32 tensor-core GEMM: C[M,N] = A[M,K] * B[N,K]^T ----------------
// Block 128x128, K-tile 32, 8 warps (2x4), warp tile 64x32 via m16n8k8 MMAs.
// MODE 0: store   MODE 1: C = Cin + acc   MODE 2: C = silu(acc)   MODE 3: C = Cin * acc
#define GSTRIDE 36            // smem row stride in floats (bank-conflict-free)
#define GTILE   (128 * GSTRIDE)
#define GEMM_SMEM_BYTES (4 * GTILE * (int)sizeof(float))  // 2 stages x (A+B)

template <int MODE>
__global__ void __launch_bounds__(256, 2) gemm_tf32_kernel(
    const float* __restrict__ A, const float* __restrict__ B,
    const float* __restrict__ Cin, float* __restrict__ C,
    int N, int K)
{
    extern __shared__ float sm[];
    float* AsBase = sm;                 // [2][128][GSTRIDE]
    float* BsBase = sm + 2 * GTILE;     // [2][128][GSTRIDE]

    const int tid  = threadIdx.x;
    const int wid  = tid >> 5;
    const int lane = tid & 31;
    const int wm   = (wid >> 2) * 64;   // warp row offset (0 or 64)
    const int wn   = (wid & 3) * 32;    // warp col offset (0,32,64,96)
    const int g    = lane >> 2;         // 0..7
    const int tg   = lane & 3;          // 0..3

    const int lr  = tid >> 3;           // 0..31 (row step 32, 4 iterations)
    const int lcv = (tid & 7) * 4;      // k-offset of the float4 this thread copies

    const float* Ag = A + ((size_t)blockIdx.y * 128 + lr) * K + lcv;
    const float* Bg = B + ((size_t)blockIdx.x * 128 + lr) * K + lcv;

    float acc[4][4][4];
#pragma unroll
    for (int i = 0; i < 4; i++)
#pragma unroll
        for (int j = 0; j < 4; j++)
#pragma unroll
            for (int r = 0; r < 4; r++) acc[i][j][r] = 0.f;

    // prologue: stage 0
    {
        float* as = AsBase;
        float* bs = BsBase;
#pragma unroll
        for (int r = 0; r < 4; r++) {
            cp_async16(as + (lr + r * 32) * GSTRIDE + lcv, Ag + (size_t)(r * 32) * K);
            cp_async16(bs + (lr + r * 32) * GSTRIDE + lcv, Bg + (size_t)(r * 32) * K);
        }
    }
    CP_COMMIT();

    int s = 0;
    for (int k0 = 0; k0 < K; k0 += 32) {
        CP_WAIT0();
        __syncthreads();

        if (k0 + 32 < K) {
            float* as = AsBase + (s ^ 1) * GTILE;
            float* bs = BsBase + (s ^ 1) * GTILE;
            const float* ag = Ag + k0 + 32;
            const float* bg = Bg + k0 + 32;
#pragma unroll
            for (int r = 0; r < 4; r++) {
                cp_async16(as + (lr + r * 32) * GSTRIDE + lcv, ag + (size_t)(r * 32) * K);
                cp_async16(bs + (lr + r * 32) * GSTRIDE + lcv, bg + (size_t)(r * 32) * K);
            }
            CP_COMMIT();
        }

        const float* as = AsBase + s * GTILE;
        const float* bs = BsBase + s * GTILE;

#pragma unroll
        for (int kk = 0; kk < 32; kk += 8) {
            uint32_t bfr[4][2];
#pragma unroll
            for (int j = 0; j < 4; j++) {
                const int n = wn + j * 8 + g;
                bfr[j][0] = cvt_tf32(bs[n * GSTRIDE + kk + tg]);
                bfr[j][1] = cvt_tf32(bs[n * GSTRIDE + kk + 4 + tg]);
            }
#pragma unroll
            for (int i = 0; i < 4; i++) {
                const int m = wm + i * 16;
                uint32_t a0 = cvt_tf32(as[(m + g) * GSTRIDE + kk + tg]);
                uint32_t a1 = cvt_tf32(as[(m + 8 + g) * GSTRIDE + kk + tg]);
                uint32_t a2 = cvt_tf32(as[(m + g) * GSTRIDE + kk + 4 + tg]);
                uint32_t a3 = cvt_tf32(as[(m + 8 + g) * GSTRIDE + kk + 4 + tg]);
#pragma unroll
                for (int j = 0; j < 4; j++)
                    mma_tf32(acc[i][j], a0, a1, a2, a3, bfr[j][0], bfr[j][1]);
            }
        }
        s ^= 1;
    }

    // epilogue
    const int row0 = blockIdx.y * 128 + wm;
    const int col0 = blockIdx.x * 128 + wn;
#pragma unroll
    for (int i = 0; i < 4; i++) {
#pragma unroll
        for (int j = 0; j < 4; j++) {
            const int r0  = row0 + i * 16 + g;
            const int col = col0 + j * 8 + 2 * tg;
#pragma unroll
            for (int half = 0; half < 2; half++) {
                const int r = r0 + half * 8;
                float vx = acc[i][j][half * 2 + 0];
                float vy = acc[i][j][half * 2 + 1];
                float* crow = C + (size_t)r * N + col;
                if (MODE == 1) {
                    const float* cin = Cin + (size_t)r * N + col;
                    vx += cin[0];
                    vy += cin[1];
                } else if (MODE == 2) {
                    vx = vx / (1.f + expf(-vx));
                    vy = vy / (1.f + expf(-vy));
                } else if (MODE == 3) {
                    const float* cin = Cin + (size_t)r * N + col;
                    vx *= cin[0];
                    vy *= cin[1];
                }
                crow[0] = vx;
                crow[1] = vy;
            }
        }
    }
}

// ---------------- causal flash attention (fp32) ----------------
#define ATT_QS   (64 * 133)
#define ATT_SMEMF (ATT_QS * 2 + 64 * 128 + 64 * 64 + 64 * 16)
#define ATT_SMEMB (ATT_SMEMF * 4)

__global__ void __launch_bounds__(256) attn_kernel(
    const float* __restrict__ q, const float* __restrict__ kg,
    const float* __restrict__ vg, float* __restrict__ o)
{
    extern __shared__ float sm[];
    float* Qs  = sm;
    float* Ks  = Qs + ATT_QS;
    float* Vs  = Ks + ATT_QS;
    float* Ps  = Vs + 64 * 128;
    float* red = Ps + 64 * 64;

    const int qt   = blockIdx.x;
    const int head = blockIdx.y;
    const int kvh  = head >> 2;
    const int t    = threadIdx.x;
    const int tx   = t & 15;
    const int ty   = t >> 4;
    const int q0   = qt * 64;
    const float scale = 0.08838834764831845f;

    {
        const int r  = t >> 2;
        const int cg = (t & 3) * 4;
        const float* src = q + ((size_t)(q0 + r)) * H_ + head * D_;
#pragma unroll
        for (int i = 0; i < 8; i++) {
            int c = cg + i * 16;
            float4 v4 = *(const float4*)(src + c);
            Qs[r * 133 + c + 0] = v4.x;
            Qs[r * 133 + c + 1] = v4.y;
            Qs[r * 133 + c + 2] = v4.z;
            Qs[r * 133 + c + 3] = v4.w;
        }
    }

    float m[4], l[4], acc[4][8];
#pragma unroll
    for (int i = 0; i < 4; i++) {
        m[i] = -1e30f;
        l[i] = 0.f;
#pragma unroll
        for (int j = 0; j < 8; j++) acc[i][j] = 0.f;
    }

    for (int kt = 0; kt <= qt; kt++) {
        __syncthreads();
        const int k0 = kt * 64;
        {
            const int r  = t >> 2;
            const int cg = (t & 3) * 4;
            const float* ksrc = kg + ((size_t)(k0 + r)) * (HKV_ * D_) + kvh * D_;
            const float* vsrc = vg + ((size_t)(k0 + r)) * (HKV_ * D_) + kvh * D_;
#pragma unroll
            for (int i = 0; i < 8; i++) {
                int c = cg + i * 16;
                float4 k4 = *(const float4*)(ksrc + c);
                Ks[r * 133 + c + 0] = k4.x;
                Ks[r * 133 + c + 1] = k4.y;
                Ks[r * 133 + c + 2] = k4.z;
                Ks[r * 133 + c + 3] = k4.w;
                float4 v4 = *(const float4*)(vsrc + c);
                *(float4*)&Vs[r * 128 + c] = v4;
            }
        }
        __syncthreads();

        float s[4][4];
#pragma unroll
        for (int i = 0; i < 4; i++)
#pragma unroll
            for (int j = 0; j < 4; j++) s[i][j] = 0.f;

#pragma unroll 8
        for (int k = 0; k < 128; k++) {
            float a[4], b[4];
#pragma unroll
            for (int i = 0; i < 4; i++) a[i] = Qs[(ty * 4 + i) * 133 + k];
#pragma unroll
            for (int j = 0; j < 4; j++) b[j] = Ks[(tx * 4 + j) * 133 + k];
#pragma unroll
            for (int i = 0; i < 4; i++)
#pragma unroll
                for (int j = 0; j < 4; j++) s[i][j] += a[i] * b[j];
        }

        float rmax[4];
#pragma unroll
        for (int i = 0; i < 4; i++) {
            const int qi = q0 + ty * 4 + i;
            rmax[i] = -1e30f;
#pragma unroll
            for (int j = 0; j < 4; j++) {
                const int ki = k0 + tx * 4 + j;
                float v = s[i][j] * scale;
                if (ki > qi) v = -1e30f;
                s[i][j] = v;
                rmax[i] = fmaxf(rmax[i], v);
            }
        }
#pragma unroll
        for (int i = 0; i < 4; i++) red[(ty * 4 + i) * 16 + tx] = rmax[i];
        __syncthreads();

        float mnew[4], alpha[4];
#pragma unroll
        for (int i = 0; i < 4; i++) {
            float mx = m[i];
#pragma unroll
            for (int x2 = 0; x2 < 16; x2++) mx = fmaxf(mx, red[(ty * 4 + i) * 16 + x2]);
            mnew[i]  = mx;
            alpha[i] = expf(m[i] - mx);
            m[i]     = mx;
        }

        float rsum[4];
#pragma unroll
        for (int i = 0; i < 4; i++) {
            rsum[i] = 0.f;
#pragma unroll
            for (int j = 0; j < 4; j++) {
                float p = expf(s[i][j] - mnew[i]);
                s[i][j] = p;
                rsum[i] += p;
            }
        }
        __syncthreads();
#pragma unroll
        for (int i = 0; i < 4; i++) {
            red[(ty * 4 + i) * 16 + tx] = rsum[i];
#pragma unroll
            for (int j = 0; j < 4; j++)
                Ps[(ty * 4 + i) * 64 + tx * 4 + j] = s[i][j];
        }
        __syncthreads();
#pragma unroll
        for (int i = 0; i < 4; i++) {
            float sum = 0.f;
#pragma unroll
            for (int x2 = 0; x2 < 16; x2++) sum += red[(ty * 4 + i) * 16 + x2];
            l[i] = l[i] * alpha[i] + sum;
#pragma unroll
            for (int j = 0; j < 8; j++) acc[i][j] *= alpha[i];
        }

#pragma unroll 4
        for (int k = 0; k < 64; k++) {
            float p4[4];
#pragma unroll
            for (int i = 0; i < 4; i++) p4[i] = Ps[(ty * 4 + i) * 64 + k];
            float4 v0 = *(const float4*)&Vs[k * 128 + tx * 8];
            float4 v1 = *(const float4*)&Vs[k * 128 + tx * 8 + 4];
#pragma unroll
            for (int i = 0; i < 4; i++) {
                acc[i][0] += p4[i] * v0.x;
                acc[i][1] += p4[i] * v0.y;
                acc[i][2] += p4[i] * v0.z;
                acc[i][3] += p4[i] * v0.w;
                acc[i][4] += p4[i] * v1.x;
                acc[i][5] += p4[i] * v1.y;
                acc[i][6] += p4[i] * v1.z;
                acc[i][7] += p4[i] * v1.w;
            }
        }
    }

#pragma unroll
    for (int i = 0; i < 4; i++) {
        const float inv = 1.f / l[i];
        float* dst = o + (size_t)(q0 + ty * 4 + i) * H_ + head * D_ + tx * 8;
        float4 o0 = make_float4(acc[i][0] * inv, acc[i][1] * inv, acc[i][2] * inv, acc[i][3] * inv);
        float4 o1 = make_float4(acc[i][4] * inv, acc[i][5] * inv, acc[i][6] * inv, acc[i][7] * inv);
        *(float4*)(dst)     = o0;
        *(float4*)(dst + 4) = o1;
    }
}

// ---------------- launch ----------------
extern "C" void kernel_launch(void* const* d_in, const int* in_sizes, int n_in,
                              void* d_out, int out_size)
{
    (void)in_sizes; (void)n_in; (void)out_size;
    const float* x      = (const float*)d_in[0];
    const int*   pos    = (const int*)  d_in[1];
    const float* w_q    = (const float*)d_in[2];
    const float* w_k    = (const float*)d_in[3];
    const float* w_v    = (const float*)d_in[4];
    const float* w_o    = (const float*)d_in[5];
    const float* w_gate = (const float*)d_in[6];
    const float* w_up   = (const float*)d_in[7];
    const float* w_down = (const float*)d_in[8];
    const float* rms1   = (const float*)d_in[9];
    const float* rms2   = (const float*)d_in[10];
    float* out = (float*)d_out;

    float *h, *q, *k, *v, *attn, *x1, *gate, *gu;
    cudaGetSymbolAddress((void**)&h,    g_h);
    cudaGetSymbolAddress((void**)&q,    g_q);
    cudaGetSymbolAddress((void**)&k,    g_k);
    cudaGetSymbolAddress((void**)&v,    g_v);
    cudaGetSymbolAddress((void**)&attn, g_attn);
    cudaGetSymbolAddress((void**)&x1,   g_x1);
    cudaGetSymbolAddress((void**)&gate, g_gate);
    cudaGetSymbolAddress((void**)&gu,   g_gu);

    cudaFuncSetAttribute(attn_kernel, cudaFuncAttributeMaxDynamicSharedMemorySize, ATT_SMEMB);
    cudaFuncSetAttribute(gemm_tf32_kernel<0>, cudaFuncAttributeMaxDynamicSharedMemorySize, GEMM_SMEM_BYTES);
    cudaFuncSetAttribute(gemm_tf32_kernel<1>, cudaFuncAttributeMaxDynamicSharedMemorySize, GEMM_SMEM_BYTES);
    cudaFuncSetAttribute(gemm_tf32_kernel<2>, cudaFuncAttributeMaxDynamicSharedMemorySize, GEMM_SMEM_BYTES);
    cudaFuncSetAttribute(gemm_tf32_kernel<3>, cudaFuncAttributeMaxDynamicSharedMemorySize, GEMM_SMEM_BYTES);

    // 1. h = rmsnorm(x) * rms1
    rmsnorm_kernel<<<T_, 256>>>(x, rms1, h);
    // 2. q/k/v projections
    gemm_tf32_kernel<0><<<dim3(H_ / 128, T_ / 128), 256, GEMM_SMEM_BYTES>>>(h, w_q, nullptr, q, H_, H_);
    gemm_tf32_kernel<0><<<dim3((HKV_ * D_) / 128, T_ / 128), 256, GEMM_SMEM_BYTES>>>(h, w_k, nullptr, k, HKV_ * D_, H_);
    gemm_tf32_kernel<0><<<dim3((HKV_ * D_) / 128, T_ / 128), 256, GEMM_SMEM_BYTES>>>(h, w_v, nullptr, v, HKV_ * D_, H_);
    // 3. RoPE
    rope_kernel<<<dim3(T_, HQ_), 64>>>(q, pos, HQ_);
    rope_kernel<<<dim3(T_, HKV_), 64>>>(k, pos, HKV_);
    // 4. causal attention
    attn_kernel<<<dim3(T_ / 64, HQ_), 256, ATT_SMEMB>>>(q, k, v, attn);
    // 5. x1 = x + attn @ w_o^T
    gemm_tf32_kernel<1><<<dim3(H_ / 128, T_ / 128), 256, GEMM_SMEM_BYTES>>>(attn, w_o, x, x1, H_, H_);
    // 6. h = rmsnorm(x1) * rms2
    rmsnorm_kernel<<<T_, 256>>>(x1, rms2, h);
    // 7. gate = silu(h @ w_gate^T)
    gemm_tf32_kernel<2><<<dim3(I_ / 128, T_ / 128), 256, GEMM_SMEM_BYTES>>>(h, w_gate, nullptr, gate, I_, H_);
    // 8. gu = gate * (h @ w_up^T)
    gemm_tf32_kernel<3><<<dim3(I_ / 128, T_ / 128), 256, GEMM_SMEM_BYTES>>>(h, w_up, gate, gu, I_, H_);
    // 9. out = x1 + gu @ w_down^T
    gemm_tf32_kernel<1><<<dim3(H_ / 128, T_ / 128), 256, GEMM_SMEM_BYTES>>>(gu, w_down, x1, out, H_, I_);
}

// round 5
// speedup vs baseline: 4.3816x; 1.5335x over previous
#include <cuda_runtime.h>
#include <cuda_fp16.h>
#include <cstddef>
#include <cstdint>
#include <math.h>

// ---------------- problem constants ----------------
#define T_  2048
#define H_  4096
#define HQ_ 32
#define HKV_ 8
#define D_  128
#define I_  14336

// ---------------- scratch (device globals; no allocation allowed) ----------------
__device__ __half g_h   [T_ * H_];            // rmsnorm out (fp16, both norms)
__device__ float  g_q   [T_ * HQ_ * D_];
__device__ float  g_k   [T_ * HKV_ * D_];
__device__ float  g_v   [T_ * HKV_ * D_];
__device__ __half g_attn[T_ * H_];            // attention out (fp16)
__device__ float  g_x1  [T_ * H_];
__device__ float  g_gate[T_ * (size_t)I_];
__device__ __half g_gu  [T_ * (size_t)I_];
// fp16 weight copies
__device__ __half g_wq[(size_t)H_ * H_];
__device__ __half g_wk[(size_t)(HKV_ * D_) * H_];
__device__ __half g_wv[(size_t)(HKV_ * D_) * H_];
__device__ __half g_wo[(size_t)H_ * H_];
__device__ __half g_wg[(size_t)I_ * H_];
__device__ __half g_wu[(size_t)I_ * H_];
__device__ __half g_wd[(size_t)H_ * I_];

// ---------------- helpers ----------------
__device__ __forceinline__ uint32_t smem_u32(const void* p) {
    return (uint32_t)__cvta_generic_to_shared(p);
}
__device__ __forceinline__ void cp_async16(uint32_t saddr, const void* gmem) {
    asm volatile("cp.async.cg.shared.global [%0], [%1], 16;\n" :: "r"(saddr), "l"(gmem));
}
#define CP_COMMIT() asm volatile("cp.async.commit_group;\n" ::: "memory")

__device__ __forceinline__ void ldsm4(uint32_t& r0, uint32_t& r1, uint32_t& r2,
                                      uint32_t& r3, uint32_t addr) {
    asm volatile("ldmatrix.sync.aligned.m8n8.x4.shared.b16 {%0,%1,%2,%3}, [%4];"
                 : "=r"(r0), "=r"(r1), "=r"(r2), "=r"(r3) : "r"(addr));
}
__device__ __forceinline__ void mma_f16(float* c,
    uint32_t a0, uint32_t a1, uint32_t a2, uint32_t a3, uint32_t b0, uint32_t b1)
{
    asm volatile(
        "mma.sync.aligned.m16n8k16.row.col.f32.f16.f16.f32 "
        "{%0,%1,%2,%3}, {%4,%5,%6,%7}, {%8,%9}, {%0,%1,%2,%3};"
        : "+f"(c[0]), "+f"(c[1]), "+f"(c[2]), "+f"(c[3])
        : "r"(a0), "r"(a1), "r"(a2), "r"(a3), "r"(b0), "r"(b1));
}

// ---------------- weight convert fp32 -> fp16 ----------------
__global__ void __launch_bounds__(256) f2h_kernel(
    const float4* __restrict__ in, __half2* __restrict__ out, int n4)
{
    int i = blockIdx.x * 256 + threadIdx.x;
    if (i < n4) {
        float4 v = in[i];
        out[2 * i]     = __floats2half2_rn(v.x, v.y);
        out[2 * i + 1] = __floats2half2_rn(v.z, v.w);
    }
}

// ---------------- RMSNorm (fp16 output) ----------------
__global__ void __launch_bounds__(256) rmsnorm_kernel(
    const float* __restrict__ x, const float* __restrict__ w, __half* __restrict__ out)
{
    const int row = blockIdx.x;
    const float4* xv = (const float4*)(x + (size_t)row * H_);
    const float4* wv = (const float4*)w;
    __half2* ov = (__half2*)(out + (size_t)row * H_);

    float4 buf[4];
    float ss = 0.f;
#pragma unroll
    for (int i = 0; i < 4; i++) {
        float4 v = xv[threadIdx.x + i * 256];
        buf[i] = v;
        ss += v.x * v.x + v.y * v.y + v.z * v.z + v.w * v.w;
    }
#pragma unroll
    for (int o = 16; o; o >>= 1) ss += __shfl_xor_sync(0xffffffffu, ss, o);

    __shared__ float wsum[8];
    __shared__ float s_inv;
    if ((threadIdx.x & 31) == 0) wsum[threadIdx.x >> 5] = ss;
    __syncthreads();
    if (threadIdx.x == 0) {
        float tot = 0.f;
#pragma unroll
        for (int i = 0; i < 8; i++) tot += wsum[i];
        s_inv = rsqrtf(tot * (1.f / (float)H_) + 1e-5f);
    }
    __syncthreads();
    const float inv = s_inv;
#pragma unroll
    for (int i = 0; i < 4; i++) {
        float4 v = buf[i];
        float4 ww = wv[threadIdx.x + i * 256];
        ov[(threadIdx.x + i * 256) * 2]     = __floats2half2_rn(v.x * inv * ww.x, v.y * inv * ww.y);
        ov[(threadIdx.x + i * 256) * 2 + 1] = __floats2half2_rn(v.z * inv * ww.z, v.w * inv * ww.w);
    }
}

// ---------------- RoPE (in place, fp32) ----------------
__global__ void rope_kernel(float* __restrict__ x, const int* __restrict__ pos, int nheads)
{
    const int tt = blockIdx.x;
    const int h  = blockIdx.y;
    const int j  = threadIdx.x;   // 0..63
    const float p = (float)pos[tt];
    const float invf = expf(-(float)j * 0.20503692777194262f);
    const float freq = p * invf;
    float s, c;
    sincosf(freq, &s, &c);
    float* base = x + ((size_t)tt * nheads + h) * D_ + j;
    const float x1v = base[0];
    const float x2v = base[64];
    base[0]  = x1v * c - x2v * s;
    base[64] = x2v * c + x1v * s;
}

// ---------------- fp16 tensor-core GEMM: C[M,N] = A[M,K] * B[N,K]^T ----------------
// CTA 128x128, K-tile 64 halves (=128B rows, SW128), 3-stage cp.async, 8 warps 2x4,
// warp tile 64x32, ldmatrix fragments.
// MODE 0: store  1: C=Cin+acc  2: C=silu(acc)  3: C=Cin*acc
// OUTH: 1 -> fp16 output, 0 -> fp32 output
#define STAGE_A 16384
#define STAGE_BYTES 32768
#define GEMM_SMEM (3 * STAGE_BYTES)

template <int MODE, int OUTH>
__global__ void __launch_bounds__(256, 2) gemm_f16_kernel(
    const __half* __restrict__ A, const __half* __restrict__ B,
    const float* __restrict__ Cin, void* __restrict__ Cv, int N, int K)
{
    extern __shared__ __align__(1024) char smem[];
    const uint32_t sbase = smem_u32(smem);
    const int tid  = threadIdx.x;
    const int wid  = tid >> 5;
    const int lane = tid & 31;
    const int warpM = (wid >> 2) * 64;
    const int warpN = (wid & 3) * 32;
    const size_t arow0 = (size_t)blockIdx.y * 128;
    const size_t brow0 = (size_t)blockIdx.x * 128;
    const int ntiles = K >> 6;

    // cp.async assignment: thread -> row tid>>1, 4 consecutive 16B chunks
    const int lrow = tid >> 1;
    const int lch  = (tid & 1) * 4;
    const __half* Ag = A + (arow0 + lrow) * K + lch * 8;
    const __half* Bg = B + (brow0 + lrow) * K + lch * 8;
    uint32_t s_off[4];
#pragma unroll
    for (int i = 0; i < 4; i++) {
        uint32_t o = (uint32_t)(lrow * 128 + (lch + i) * 16);
        s_off[i] = o ^ ((o >> 3) & 0x70);
    }

#define LOADT(t, slot)                                                   \
    {                                                                    \
        const uint32_t sa = sbase + (slot) * STAGE_BYTES;                \
        const __half* ag = Ag + (size_t)(t) * 64;                        \
        const __half* bg = Bg + (size_t)(t) * 64;                        \
        _Pragma("unroll")                                                \
        for (int i = 0; i < 4; i++) {                                    \
            cp_async16(sa + s_off[i], ag + i * 8);                       \
            cp_async16(sa + STAGE_A + s_off[i], bg + i * 8);             \
        }                                                                \
    }

    // ldmatrix per-thread row bases + swizzle masks (XOR k-offset into bits [6:4])
    uint32_t aRow[4], aMask[4], bRow[2], bMask[2];
    const int kbA = (lane >> 4) * 16;          // bytes: lanes>=16 take k+8 matrices
    {
        const int r = lane & 15;
#pragma unroll
        for (int mi = 0; mi < 4; mi++) {
            uint32_t o = (uint32_t)((warpM + mi * 16 + r) * 128);
            aRow[mi]  = o;
            aMask[mi] = (o >> 3) & 0x70;
        }
    }
    const int rn  = (lane & 7) + ((lane >> 4) << 3);
    const int kbB = ((lane >> 3) & 1) * 16;
    {
#pragma unroll
        for (int ni = 0; ni < 2; ni++) {
            uint32_t o = (uint32_t)((warpN + ni * 16 + rn) * 128);
            bRow[ni]  = o;
            bMask[ni] = (o >> 3) & 0x70;
        }
    }

    float acc[4][4][4];
#pragma unroll
    for (int mi = 0; mi < 4; mi++)
#pragma unroll
        for (int nj = 0; nj < 4; nj++)
#pragma unroll
            for (int r = 0; r < 4; r++) acc[mi][nj][r] = 0.f;

    LOADT(0, 0); CP_COMMIT();
    LOADT(1, 1); CP_COMMIT();

    for (int t = 0; t < ntiles; t++) {
        __syncthreads();                     // slot (t+2)%3 == (t-1)%3 free for overwrite
        if (t + 2 < ntiles) { LOADT(t + 2, (t + 2) % 3); }
        CP_COMMIT();
        asm volatile("cp.async.wait_group 2;\n" ::: "memory");  // tile t resident
        __syncthreads();

        const uint32_t sa = sbase + (t % 3) * STAGE_BYTES;
#pragma unroll
        for (int ks = 0; ks < 4; ks++) {
            uint32_t b[2][4];
#pragma unroll
            for (int ni = 0; ni < 2; ni++)
                ldsm4(b[ni][0], b[ni][1], b[ni][2], b[ni][3],
                      sa + STAGE_A + bRow[ni] + (((uint32_t)(kbB + ks * 32)) ^ bMask[ni]));
#pragma unroll
            for (int mi = 0; mi < 4; mi++) {
                uint32_t a0, a1, a2, a3;
                ldsm4(a0, a1, a2, a3,
                      sa + aRow[mi] + (((uint32_t)(kbA + ks * 32)) ^ aMask[mi]));
#pragma unroll
                for (int nj = 0; nj < 4; nj++)
                    mma_f16(acc[mi][nj], a0, a1, a2, a3,
                            b[nj >> 1][(nj & 1) * 2], b[nj >> 1][(nj & 1) * 2 + 1]);
            }
        }
    }
#undef LOADT

    // epilogue
    const int r0 = (int)arow0 + warpM + (lane >> 2);
    const int c0 = blockIdx.x * 128 + warpN + (lane & 3) * 2;
#pragma unroll
    for (int mi = 0; mi < 4; mi++) {
#pragma unroll
        for (int h = 0; h < 2; h++) {
            const int row = r0 + mi * 16 + h * 8;
#pragma unroll
            for (int nj = 0; nj < 4; nj++) {
                const int col = c0 + nj * 8;
                float vx = acc[mi][nj][h * 2 + 0];
                float vy = acc[mi][nj][h * 2 + 1];
                if (MODE == 1) {
                    const float* cin = Cin + (size_t)row * N + col;
                    vx += cin[0];
                    vy += cin[1];
                } else if (MODE == 2) {
                    vx = vx / (1.f + expf(-vx));
                    vy = vy / (1.f + expf(-vy));
                } else if (MODE == 3) {
                    const float* cin = Cin + (size_t)row * N + col;
                    vx *= cin[0];
                    vy *= cin[1];
                }
                if (OUTH) {
                    __half2* dst = (__half2*)((__half*)Cv + (size_t)row * N + col);
                    *dst = __floats2half2_rn(vx, vy);
                } else {
                    float2* dst = (float2*)((float*)Cv + (size_t)row * N + col);
                    *dst = make_float2(vx, vy);
                }
            }
        }
    }
}

// ---------------- causal flash attention (fp32, fp16 output) ----------------
#define ATT_QS   (64 * 133)
#define ATT_SMEMF (ATT_QS * 2 + 64 * 128 + 64 * 64 + 64 * 16)
#define ATT_SMEMB (ATT_SMEMF * 4)

__global__ void __launch_bounds__(256) attn_kernel(
    const float* __restrict__ q, const float* __restrict__ kg,
    const float* __restrict__ vg, __half* __restrict__ o)
{
    extern __shared__ float sm[];
    float* Qs  = sm;
    float* Ks  = Qs + ATT_QS;
    float* Vs  = Ks + ATT_QS;
    float* Ps  = Vs + 64 * 128;
    float* red = Ps + 64 * 64;

    const int qt   = blockIdx.x;
    const int head = blockIdx.y;
    const int kvh  = head >> 2;
    const int t    = threadIdx.x;
    const int tx   = t & 15;
    const int ty   = t >> 4;
    const int q0   = qt * 64;
    const float scale = 0.08838834764831845f;

    {
        const int r  = t >> 2;
        const int cg = (t & 3) * 4;
        const float* src = q + ((size_t)(q0 + r)) * H_ + head * D_;
#pragma unroll
        for (int i = 0; i < 8; i++) {
            int c = cg + i * 16;
            float4 v4 = *(const float4*)(src + c);
            Qs[r * 133 + c + 0] = v4.x;
            Qs[r * 133 + c + 1] = v4.y;
            Qs[r * 133 + c + 2] = v4.z;
            Qs[r * 133 + c + 3] = v4.w;
        }
    }

    float m[4], l[4], acc[4][8];
#pragma unroll
    for (int i = 0; i < 4; i++) {
        m[i] = -1e30f;
        l[i] = 0.f;
#pragma unroll
        for (int j = 0; j < 8; j++) acc[i][j] = 0.f;
    }

    for (int kt = 0; kt <= qt; kt++) {
        __syncthreads();
        const int k0 = kt * 64;
        {
            const int r  = t >> 2;
            const int cg = (t & 3) * 4;
            const float* ksrc = kg + ((size_t)(k0 + r)) * (HKV_ * D_) + kvh * D_;
            const float* vsrc = vg + ((size_t)(k0 + r)) * (HKV_ * D_) + kvh * D_;
#pragma unroll
            for (int i = 0; i < 8; i++) {
                int c = cg + i * 16;
                float4 k4 = *(const float4*)(ksrc + c);
                Ks[r * 133 + c + 0] = k4.x;
                Ks[r * 133 + c + 1] = k4.y;
                Ks[r * 133 + c + 2] = k4.z;
                Ks[r * 133 + c + 3] = k4.w;
                float4 v4 = *(const float4*)(vsrc + c);
                *(float4*)&Vs[r * 128 + c] = v4;
            }
        }
        __syncthreads();

        float s[4][4];
#pragma unroll
        for (int i = 0; i < 4; i++)
#pragma unroll
            for (int j = 0; j < 4; j++) s[i][j] = 0.f;

#pragma unroll 8
        for (int k = 0; k < 128; k++) {
            float a[4], b[4];
#pragma unroll
            for (int i = 0; i < 4; i++) a[i] = Qs[(ty * 4 + i) * 133 + k];
#pragma unroll
            for (int j = 0; j < 4; j++) b[j] = Ks[(tx * 4 + j) * 133 + k];
#pragma unroll
            for (int i = 0; i < 4; i++)
#pragma unroll
                for (int j = 0; j < 4; j++) s[i][j] += a[i] * b[j];
        }

        float rmax[4];
#pragma unroll
        for (int i = 0; i < 4; i++) {
            const int qi = q0 + ty * 4 + i;
            rmax[i] = -1e30f;
#pragma unroll
            for (int j = 0; j < 4; j++) {
                const int ki = k0 + tx * 4 + j;
                float v = s[i][j] * scale;
                if (ki > qi) v = -1e30f;
                s[i][j] = v;
                rmax[i] = fmaxf(rmax[i], v);
            }
        }
#pragma unroll
        for (int i = 0; i < 4; i++) red[(ty * 4 + i) * 16 + tx] = rmax[i];
        __syncthreads();

        float mnew[4], alpha[4];
#pragma unroll
        for (int i = 0; i < 4; i++) {
            float mx = m[i];
#pragma unroll
            for (int x2 = 0; x2 < 16; x2++) mx = fmaxf(mx, red[(ty * 4 + i) * 16 + x2]);
            mnew[i]  = mx;
            alpha[i] = expf(m[i] - mx);
            m[i]     = mx;
        }

        float rsum[4];
#pragma unroll
        for (int i = 0; i < 4; i++) {
            rsum[i] = 0.f;
#pragma unroll
            for (int j = 0; j < 4; j++) {
                float p = expf(s[i][j] - mnew[i]);
                s[i][j] = p;
                rsum[i] += p;
            }
        }
        __syncthreads();
#pragma unroll
        for (int i = 0; i < 4; i++) {
            red[(ty * 4 + i) * 16 + tx] = rsum[i];
#pragma unroll
            for (int j = 0; j < 4; j++)
                Ps[(ty * 4 + i) * 64 + tx * 4 + j] = s[i][j];
        }
        __syncthreads();
#pragma unroll
        for (int i = 0; i < 4; i++) {
            float sum = 0.f;
#pragma unroll
            for (int x2 = 0; x2 < 16; x2++) sum += red[(ty * 4 + i) * 16 + x2];
            l[i] = l[i] * alpha[i] + sum;
#pragma unroll
            for (int j = 0; j < 8; j++) acc[i][j] *= alpha[i];
        }

#pragma unroll 4
        for (int k = 0; k < 64; k++) {
            float p4[4];
#pragma unroll
            for (int i = 0; i < 4; i++) p4[i] = Ps[(ty * 4 + i) * 64 + k];
            float4 v0 = *(const float4*)&Vs[k * 128 + tx * 8];
            float4 v1 = *(const float4*)&Vs[k * 128 + tx * 8 + 4];
#pragma unroll
            for (int i = 0; i < 4; i++) {
                acc[i][0] += p4[i] * v0.x;
                acc[i][1] += p4[i] * v0.y;
                acc[i][2] += p4[i] * v0.z;
                acc[i][3] += p4[i] * v0.w;
                acc[i][4] += p4[i] * v1.x;
                acc[i][5] += p4[i] * v1.y;
                acc[i][6] += p4[i] * v1.z;
                acc[i][7] += p4[i] * v1.w;
            }
        }
    }

#pragma unroll
    for (int i = 0; i < 4; i++) {
        const float inv = 1.f / l[i];
        __half2* dst = (__half2*)(o + (size_t)(q0 + ty * 4 + i) * H_ + head * D_ + tx * 8);
        dst[0] = __floats2half2_rn(acc[i][0] * inv, acc[i][1] * inv);
        dst[1] = __floats2half2_rn(acc[i][2] * inv, acc[i][3] * inv);
        dst[2] = __floats2half2_rn(acc[i][4] * inv, acc[i][5] * inv);
        dst[3] = __floats2half2_rn(acc[i][6] * inv, acc[i][7] * inv);
    }
}

// ---------------- launch ----------------
static inline void conv_w(const float* src, __half* dst, size_t n) {
    int n4 = (int)(n / 4);
    f2h_kernel<<<(n4 + 255) / 256, 256>>>((const float4*)src, (__half2*)dst, n4);
}

extern "C" void kernel_launch(void* const* d_in, const int* in_sizes, int n_in,
                              void* d_out, int out_size)
{
    (void)in_sizes; (void)n_in; (void)out_size;
    const float* x      = (const float*)d_in[0];
    const int*   pos    = (const int*)  d_in[1];
    const float* w_q    = (const float*)d_in[2];
    const float* w_k    = (const float*)d_in[3];
    const float* w_v    = (const float*)d_in[4];
    const float* w_o    = (const float*)d_in[5];
    const float* w_gate = (const float*)d_in[6];
    const float* w_up   = (const float*)d_in[7];
    const float* w_down = (const float*)d_in[8];
    const float* rms1   = (const float*)d_in[9];
    const float* rms2   = (const float*)d_in[10];
    float* out = (float*)d_out;

    __half *h, *attn, *gu, *wq, *wk, *wv, *wo, *wg, *wu, *wd;
    float *q, *k, *v, *x1, *gate;
    cudaGetSymbolAddress((void**)&h,    g_h);
    cudaGetSymbolAddress((void**)&q,    g_q);
    cudaGetSymbolAddress((void**)&k,    g_k);
    cudaGetSymbolAddress((void**)&v,    g_v);
    cudaGetSymbolAddress((void**)&attn, g_attn);
    cudaGetSymbolAddress((void**)&x1,   g_x1);
    cudaGetSymbolAddress((void**)&gate, g_gate);
    cudaGetSymbolAddress((void**)&gu,   g_gu);
    cudaGetSymbolAddress((void**)&wq,   g_wq);
    cudaGetSymbolAddress((void**)&wk,   g_wk);
    cudaGetSymbolAddress((void**)&wv,   g_wv);
    cudaGetSymbolAddress((void**)&wo,   g_wo);
    cudaGetSymbolAddress((void**)&wg,   g_wg);
    cudaGetSymbolAddress((void**)&wu,   g_wu);
    cudaGetSymbolAddress((void**)&wd,   g_wd);

    cudaFuncSetAttribute(attn_kernel, cudaFuncAttributeMaxDynamicSharedMemorySize, ATT_SMEMB);
    cudaFuncSetAttribute(gemm_f16_kernel<0,0>, cudaFuncAttributeMaxDynamicSharedMemorySize, GEMM_SMEM);
    cudaFuncSetAttribute(gemm_f16_kernel<1,0>, cudaFuncAttributeMaxDynamicSharedMemorySize, GEMM_SMEM);
    cudaFuncSetAttribute(gemm_f16_kernel<2,0>, cudaFuncAttributeMaxDynamicSharedMemorySize, GEMM_SMEM);
    cudaFuncSetAttribute(gemm_f16_kernel<3,1>, cudaFuncAttributeMaxDynamicSharedMemorySize, GEMM_SMEM);

    // 0. weights -> fp16
    conv_w(w_q,    wq, (size_t)H_ * H_);
    conv_w(w_k,    wk, (size_t)(HKV_ * D_) * H_);
    conv_w(w_v,    wv, (size_t)(HKV_ * D_) * H_);
    conv_w(w_o,    wo, (size_t)H_ * H_);
    conv_w(w_gate, wg, (size_t)I_ * H_);
    conv_w(w_up,   wu, (size_t)I_ * H_);
    conv_w(w_down, wd, (size_t)H_ * I_);

    // 1. h = rmsnorm(x) * rms1  (fp16)
    rmsnorm_kernel<<<T_, 256>>>(x, rms1, h);
    // 2. q/k/v projections (fp16 MMA, fp32 out)
    gemm_f16_kernel<0,0><<<dim3(H_ / 128, T_ / 128), 256, GEMM_SMEM>>>(h, wq, nullptr, q, H_, H_);
    gemm_f16_kernel<0,0><<<dim3((HKV_ * D_) / 128, T_ / 128), 256, GEMM_SMEM>>>(h, wk, nullptr, k, HKV_ * D_, H_);
    gemm_f16_kernel<0,0><<<dim3((HKV_ * D_) / 128, T_ / 128), 256, GEMM_SMEM>>>(h, wv, nullptr, v, HKV_ * D_, H_);
    // 3. RoPE
    rope_kernel<<<dim3(T_, HQ_), 64>>>(q, pos, HQ_);
    rope_kernel<<<dim3(T_, HKV_), 64>>>(k, pos, HKV_);
    // 4. causal attention (fp16 out)
    attn_kernel<<<dim3(T_ / 64, HQ_), 256, ATT_SMEMB>>>(q, k, v, attn);
    // 5. x1 = x + attn @ w_o^T
    gemm_f16_kernel<1,0><<<dim3(H_ / 128, T_ / 128), 256, GEMM_SMEM>>>(attn, wo, x, x1, H_, H_);
    // 6. h = rmsnorm(x1) * rms2 (fp16)
    rmsnorm_kernel<<<T_, 256>>>(x1, rms2, h);
    // 7. gate = silu(h @ w_gate^T)  (fp32)
    gemm_f16_kernel<2,0><<<dim3(I_ / 128, T_ / 128), 256, GEMM_SMEM>>>(h, wg, nullptr, gate, I_, H_);
    // 8. gu = gate * (h @ w_up^T)  (fp16)
    gemm_f16_kernel<3,1><<<dim3(I_ / 128, T_ / 128), 256, GEMM_SMEM>>>(h, wu, gate, gu, I_, H_);
    // 9. out = x1 + gu @ w_down^T
    gemm_f16_kernel<1,0><<<dim3(H_ / 128, T_ / 128), 256, GEMM_SMEM>>>(gu, wd, x1, out, H_, I_);
}

// round 6
// speedup vs baseline: 5.6889x; 1.2984x over previous
#include <cuda_runtime.h>
#include <cuda_fp16.h>
#include <cstddef>
#include <cstdint>
#include <math.h>

// ---------------- problem constants ----------------
#define T_  2048
#define H_  4096
#define HQ_ 32
#define HKV_ 8
#define D_  128
#define I_  14336

// ---------------- scratch (device globals; no allocation allowed) ----------------
__device__ __half g_h   [T_ * H_];            // rmsnorm out (fp16)
__device__ float  g_q   [T_ * HQ_ * D_];      // q proj fp32 (pre-rope)
__device__ float  g_k   [T_ * HKV_ * D_];     // k proj fp32 (pre-rope)
__device__ __half g_qh  [T_ * HQ_ * D_];      // q fp16 post-rope
__device__ __half g_kh  [T_ * HKV_ * D_];     // k fp16 post-rope
__device__ __half g_vh  [T_ * HKV_ * D_];     // v fp16
__device__ __half g_attn[T_ * H_];            // attention out (fp16)
__device__ float  g_x1  [T_ * H_];
__device__ float  g_gate[T_ * (size_t)I_];
__device__ __half g_gu  [T_ * (size_t)I_];
// fp16 weight copies
__device__ __half g_wq[(size_t)H_ * H_];
__device__ __half g_wk[(size_t)(HKV_ * D_) * H_];
__device__ __half g_wv[(size_t)(HKV_ * D_) * H_];
__device__ __half g_wo[(size_t)H_ * H_];
__device__ __half g_wg[(size_t)I_ * H_];
__device__ __half g_wu[(size_t)I_ * H_];
__device__ __half g_wd[(size_t)H_ * I_];

// ---------------- helpers ----------------
__device__ __forceinline__ uint32_t smem_u32(const void* p) {
    return (uint32_t)__cvta_generic_to_shared(p);
}
__device__ __forceinline__ void cp_async16(uint32_t saddr, const void* gmem) {
    asm volatile("cp.async.cg.shared.global [%0], [%1], 16;\n" :: "r"(saddr), "l"(gmem));
}
#define CP_COMMIT() asm volatile("cp.async.commit_group;\n" ::: "memory")

__device__ __forceinline__ void ldsm4(uint32_t& r0, uint32_t& r1, uint32_t& r2,
                                      uint32_t& r3, uint32_t addr) {
    asm volatile("ldmatrix.sync.aligned.m8n8.x4.shared.b16 {%0,%1,%2,%3}, [%4];"
                 : "=r"(r0), "=r"(r1), "=r"(r2), "=r"(r3) : "r"(addr));
}
__device__ __forceinline__ void ldsm4t(uint32_t& r0, uint32_t& r1, uint32_t& r2,
                                       uint32_t& r3, uint32_t addr) {
    asm volatile("ldmatrix.sync.aligned.m8n8.x4.trans.shared.b16 {%0,%1,%2,%3}, [%4];"
                 : "=r"(r0), "=r"(r1), "=r"(r2), "=r"(r3) : "r"(addr));
}
__device__ __forceinline__ void mma_f16(float* c,
    uint32_t a0, uint32_t a1, uint32_t a2, uint32_t a3, uint32_t b0, uint32_t b1)
{
    asm volatile(
        "mma.sync.aligned.m16n8k16.row.col.f32.f16.f16.f32 "
        "{%0,%1,%2,%3}, {%4,%5,%6,%7}, {%8,%9}, {%0,%1,%2,%3};"
        : "+f"(c[0]), "+f"(c[1]), "+f"(c[2]), "+f"(c[3])
        : "r"(a0), "r"(a1), "r"(a2), "r"(a3), "r"(b0), "r"(b1));
}
__device__ __forceinline__ uint32_t packh2(float a, float b) {
    __half2 h = __floats2half2_rn(a, b);
    return *(uint32_t*)&h;
}

// ---------------- weight convert fp32 -> fp16 ----------------
__global__ void __launch_bounds__(256) f2h_kernel(
    const float4* __restrict__ in, __half2* __restrict__ out, int n4)
{
    int i = blockIdx.x * 256 + threadIdx.x;
    if (i < n4) {
        float4 v = in[i];
        out[2 * i]     = __floats2half2_rn(v.x, v.y);
        out[2 * i + 1] = __floats2half2_rn(v.z, v.w);
    }
}

// ---------------- RMSNorm (fp16 output) ----------------
__global__ void __launch_bounds__(256) rmsnorm_kernel(
    const float* __restrict__ x, const float* __restrict__ w, __half* __restrict__ out)
{
    const int row = blockIdx.x;
    const float4* xv = (const float4*)(x + (size_t)row * H_);
    const float4* wv = (const float4*)w;
    __half2* ov = (__half2*)(out + (size_t)row * H_);

    float4 buf[4];
    float ss = 0.f;
#pragma unroll
    for (int i = 0; i < 4; i++) {
        float4 v = xv[threadIdx.x + i * 256];
        buf[i] = v;
        ss += v.x * v.x + v.y * v.y + v.z * v.z + v.w * v.w;
    }
#pragma unroll
    for (int o = 16; o; o >>= 1) ss += __shfl_xor_sync(0xffffffffu, ss, o);

    __shared__ float wsum[8];
    __shared__ float s_inv;
    if ((threadIdx.x & 31) == 0) wsum[threadIdx.x >> 5] = ss;
    __syncthreads();
    if (threadIdx.x == 0) {
        float tot = 0.f;
#pragma unroll
        for (int i = 0; i < 8; i++) tot += wsum[i];
        s_inv = rsqrtf(tot * (1.f / (float)H_) + 1e-5f);
    }
    __syncthreads();
    const float inv = s_inv;
#pragma unroll
    for (int i = 0; i < 4; i++) {
        float4 v = buf[i];
        float4 ww = wv[threadIdx.x + i * 256];
        ov[(threadIdx.x + i * 256) * 2]     = __floats2half2_rn(v.x * inv * ww.x, v.y * inv * ww.y);
        ov[(threadIdx.x + i * 256) * 2 + 1] = __floats2half2_rn(v.z * inv * ww.z, v.w * inv * ww.w);
    }
}

// ---------------- RoPE: fp32 in, fp16 out ----------------
__global__ void rope_kernel(const float* __restrict__ x, const int* __restrict__ pos,
                            __half* __restrict__ out, int nheads)
{
    const int tt = blockIdx.x;
    const int h  = blockIdx.y;
    const int j  = threadIdx.x;   // 0..63
    const float p = (float)pos[tt];
    const float invf = expf(-(float)j * 0.20503692777194262f);
    const float freq = p * invf;
    float s, c;
    sincosf(freq, &s, &c);
    const float* base = x + ((size_t)tt * nheads + h) * D_ + j;
    __half* ob = out + ((size_t)tt * nheads + h) * D_ + j;
    const float x1v = base[0];
    const float x2v = base[64];
    ob[0]  = __float2half(x1v * c - x2v * s);
    ob[64] = __float2half(x2v * c + x1v * s);
}

// ---------------- fp16 tensor-core GEMM: C[M,N] = A[M,K] * B[N,K]^T ----------------
#define STAGE_A 16384
#define STAGE_BYTES 32768
#define GEMM_SMEM (3 * STAGE_BYTES)

template <int MODE, int OUTH>
__global__ void __launch_bounds__(256, 2) gemm_f16_kernel(
    const __half* __restrict__ A, const __half* __restrict__ B,
    const float* __restrict__ Cin, void* __restrict__ Cv, int N, int K)
{
    extern __shared__ __align__(1024) char smem[];
    const uint32_t sbase = smem_u32(smem);
    const int tid  = threadIdx.x;
    const int wid  = tid >> 5;
    const int lane = tid & 31;
    const int warpM = (wid >> 2) * 64;
    const int warpN = (wid & 3) * 32;
    const size_t arow0 = (size_t)blockIdx.y * 128;
    const size_t brow0 = (size_t)blockIdx.x * 128;
    const int ntiles = K >> 6;

    const int lrow = tid >> 1;
    const int lch  = (tid & 1) * 4;
    const __half* Ag = A + (arow0 + lrow) * K + lch * 8;
    const __half* Bg = B + (brow0 + lrow) * K + lch * 8;
    uint32_t s_off[4];
#pragma unroll
    for (int i = 0; i < 4; i++) {
        uint32_t o = (uint32_t)(lrow * 128 + (lch + i) * 16);
        s_off[i] = o ^ ((o >> 3) & 0x70);
    }

#define LOADT(t, slot)                                                   \
    {                                                                    \
        const uint32_t sa = sbase + (slot) * STAGE_BYTES;                \
        const __half* ag = Ag + (size_t)(t) * 64;                        \
        const __half* bg = Bg + (size_t)(t) * 64;                        \
        _Pragma("unroll")                                                \
        for (int i = 0; i < 4; i++) {                                    \
            cp_async16(sa + s_off[i], ag + i * 8);                       \
            cp_async16(sa + STAGE_A + s_off[i], bg + i * 8);             \
        }                                                                \
    }

    uint32_t aRow[4], aMask[4], bRow[2], bMask[2];
    const int kbA = (lane >> 4) * 16;
    {
        const int r = lane & 15;
#pragma unroll
        for (int mi = 0; mi < 4; mi++) {
            uint32_t o = (uint32_t)((warpM + mi * 16 + r) * 128);
            aRow[mi]  = o;
            aMask[mi] = (o >> 3) & 0x70;
        }
    }
    const int rn  = (lane & 7) + ((lane >> 4) << 3);
    const int kbB = ((lane >> 3) & 1) * 16;
    {
#pragma unroll
        for (int ni = 0; ni < 2; ni++) {
            uint32_t o = (uint32_t)((warpN + ni * 16 + rn) * 128);
            bRow[ni]  = o;
            bMask[ni] = (o >> 3) & 0x70;
        }
    }

    float acc[4][4][4];
#pragma unroll
    for (int mi = 0; mi < 4; mi++)
#pragma unroll
        for (int nj = 0; nj < 4; nj++)
#pragma unroll
            for (int r = 0; r < 4; r++) acc[mi][nj][r] = 0.f;

    LOADT(0, 0); CP_COMMIT();
    LOADT(1, 1); CP_COMMIT();

    for (int t = 0; t < ntiles; t++) {
        __syncthreads();
        if (t + 2 < ntiles) { LOADT(t + 2, (t + 2) % 3); }
        CP_COMMIT();
        asm volatile("cp.async.wait_group 2;\n" ::: "memory");
        __syncthreads();

        const uint32_t sa = sbase + (t % 3) * STAGE_BYTES;
#pragma unroll
        for (int ks = 0; ks < 4; ks++) {
            uint32_t b[2][4];
#pragma unroll
            for (int ni = 0; ni < 2; ni++)
                ldsm4(b[ni][0], b[ni][1], b[ni][2], b[ni][3],
                      sa + STAGE_A + bRow[ni] + (((uint32_t)(kbB + ks * 32)) ^ bMask[ni]));
#pragma unroll
            for (int mi = 0; mi < 4; mi++) {
                uint32_t a0, a1, a2, a3;
                ldsm4(a0, a1, a2, a3,
                      sa + aRow[mi] + (((uint32_t)(kbA + ks * 32)) ^ aMask[mi]));
#pragma unroll
                for (int nj = 0; nj < 4; nj++)
                    mma_f16(acc[mi][nj], a0, a1, a2, a3,
                            b[nj >> 1][(nj & 1) * 2], b[nj >> 1][(nj & 1) * 2 + 1]);
            }
        }
    }
#undef LOADT

    const int r0 = (int)arow0 + warpM + (lane >> 2);
    const int c0 = blockIdx.x * 128 + warpN + (lane & 3) * 2;
#pragma unroll
    for (int mi = 0; mi < 4; mi++) {
#pragma unroll
        for (int h = 0; h < 2; h++) {
            const int row = r0 + mi * 16 + h * 8;
#pragma unroll
            for (int nj = 0; nj < 4; nj++) {
                const int col = c0 + nj * 8;
                float vx = acc[mi][nj][h * 2 + 0];
                float vy = acc[mi][nj][h * 2 + 1];
                if (MODE == 1) {
                    const float* cin = Cin + (size_t)row * N + col;
                    vx += cin[0];
                    vy += cin[1];
                } else if (MODE == 2) {
                    vx = vx / (1.f + expf(-vx));
                    vy = vy / (1.f + expf(-vy));
                } else if (MODE == 3) {
                    const float* cin = Cin + (size_t)row * N + col;
                    vx *= cin[0];
                    vy *= cin[1];
                }
                if (OUTH) {
                    __half2* dst = (__half2*)((__half*)Cv + (size_t)row * N + col);
                    *dst = __floats2half2_rn(vx, vy);
                } else {
                    float2* dst = (float2*)((float*)Cv + (size_t)row * N + col);
                    *dst = make_float2(vx, vy);
                }
            }
        }
    }
}

// ---------------- fp16 tensor-core causal flash attention ----------------
// CTA: 128 q-rows x 1 head, 8 warps (16 rows each). 64-key K/V tiles double-buffered.
// smem: Qs [2 seg][128][128B] 32KB; per buf: K [2 seg][64][128B] 16KB + V 16KB.
#define AQ_OFF   0
#define AKV_OFF  32768
#define AKV_STRIDE 32768
#define ATT_SMEM (32768 + 2 * AKV_STRIDE)   // 96KB

__global__ void __launch_bounds__(256) attn16_kernel(
    const __half* __restrict__ qh, const __half* __restrict__ kh,
    const __half* __restrict__ vh, __half* __restrict__ o)
{
    extern __shared__ __align__(1024) char smem[];
    const uint32_t sbase = smem_u32(smem);
    const int tid  = threadIdx.x;
    const int wid  = tid >> 5;
    const int lane = tid & 31;
    const int bx   = blockIdx.x;
    const int head = blockIdx.y;
    const int kvh  = head >> 2;
    const int q0   = bx * 128;
    const int qr0  = q0 + wid * 16;
    const float scale = 0.08838834764831845f;

    // ---- prologue: load Q tile (2048 x 16B chunks) ----
#pragma unroll
    for (int i = 0; i < 8; i++) {
        const int chunk = tid + 256 * i;
        const int seg = chunk >> 10;
        const int row = (chunk >> 3) & 127;
        const int off = chunk & 7;
        const uint32_t ro = (uint32_t)(row * 128);
        const uint32_t sw = ro + (((uint32_t)(off * 16)) ^ ((ro >> 3) & 0x70));
        cp_async16(sbase + AQ_OFF + seg * 16384 + sw,
                   qh + (size_t)(q0 + row) * (HQ_ * D_) + head * D_ + seg * 64 + off * 8);
    }
    CP_COMMIT();

#define LOADKV(kt, buf)                                                              \
    {                                                                                \
        const int k0l = (kt) * 64;                                                   \
        const uint32_t kb = sbase + AKV_OFF + (buf) * AKV_STRIDE;                    \
        _Pragma("unroll")                                                            \
        for (int i = 0; i < 4; i++) {                                                \
            const int chunk = tid + 256 * i;                                         \
            const int seg = chunk >> 9;                                              \
            const int row = (chunk >> 3) & 63;                                       \
            const int off = chunk & 7;                                               \
            const uint32_t ro = (uint32_t)(row * 128);                               \
            const uint32_t sw = ro + (((uint32_t)(off * 16)) ^ ((ro >> 3) & 0x70));  \
            const size_t gi = (size_t)(k0l + row) * (HKV_ * D_) + kvh * D_           \
                            + seg * 64 + off * 8;                                    \
            cp_async16(kb + seg * 8192 + sw, kh + gi);                               \
            cp_async16(kb + 16384 + seg * 8192 + sw, vh + gi);                       \
        }                                                                            \
    }

    LOADKV(0, 0); CP_COMMIT();

    // fragment addressing
    const int rA    = lane & 15;
    const int kbA   = (lane >> 4) * 16;
    const int rnB   = (lane & 7) + ((lane >> 4) << 3);
    const int kbB   = ((lane >> 3) & 1) * 16;
    const int rV    = (lane & 7) + ((lane >> 3) & 1) * 8;     // key row within 16
    const int dbV   = ((lane >> 4) & 1) * 16;                  // d-byte within 32

    uint32_t qf[8][4];
    float accO[16][4];
#pragma unroll
    for (int nj = 0; nj < 16; nj++)
#pragma unroll
        for (int r = 0; r < 4; r++) accO[nj][r] = 0.f;
    float m1 = -1e30f, m2 = -1e30f, l1 = 0.f, l2 = 0.f;

    const int ktmax = 2 * bx + 1;
    for (int kt = 0; kt <= ktmax; kt++) {
        if (kt < ktmax) {
            LOADKV(kt + 1, (kt + 1) & 1);
            CP_COMMIT();
            asm volatile("cp.async.wait_group 1;\n" ::: "memory");
        } else {
            asm volatile("cp.async.wait_group 0;\n" ::: "memory");
        }
        __syncthreads();

        if (kt == 0) {
            // preload Q fragments (16 rows x 128 d) once
#pragma unroll
            for (int ks = 0; ks < 8; ks++) {
                const int seg = ks >> 2;
                const uint32_t ro = (uint32_t)((wid * 16 + rA) * 128);
                const uint32_t addr = sbase + AQ_OFF + seg * 16384 + ro
                    + (((uint32_t)(kbA + (ks & 3) * 32)) ^ ((ro >> 3) & 0x70));
                ldsm4(qf[ks][0], qf[ks][1], qf[ks][2], qf[ks][3], addr);
            }
        }

        const int k0 = kt * 64;
        if (k0 <= qr0 + 15) {
            const uint32_t kbuf = sbase + AKV_OFF + (kt & 1) * AKV_STRIDE;
            // ---- S = Q K^T : 16 x 64, fp32 acc ----
            float s[8][4];
#pragma unroll
            for (int nj = 0; nj < 8; nj++)
#pragma unroll
                for (int r = 0; r < 4; r++) s[nj][r] = 0.f;

#pragma unroll
            for (int ks = 0; ks < 8; ks++) {
                const int seg = ks >> 2;
                uint32_t b[4][4];
#pragma unroll
                for (int ni = 0; ni < 4; ni++) {
                    const uint32_t ro = (uint32_t)((ni * 16 + rnB) * 128);
                    ldsm4(b[ni][0], b[ni][1], b[ni][2], b[ni][3],
                          kbuf + seg * 8192 + ro
                          + (((uint32_t)(kbB + (ks & 3) * 32)) ^ ((ro >> 3) & 0x70)));
                }
#pragma unroll
                for (int nj = 0; nj < 8; nj++)
                    mma_f16(s[nj], qf[ks][0], qf[ks][1], qf[ks][2], qf[ks][3],
                            b[nj >> 1][(nj & 1) * 2], b[nj >> 1][(nj & 1) * 2 + 1]);
            }

            // ---- mask + online softmax ----
            const int row1 = qr0 + (lane >> 2);
            const int row2 = row1 + 8;
            float rmax1 = -1e30f, rmax2 = -1e30f;
#pragma unroll
            for (int nj = 0; nj < 8; nj++) {
                const int c0 = k0 + nj * 8 + (lane & 3) * 2;
                float v0 = s[nj][0] * scale, v1 = s[nj][1] * scale;
                float v2 = s[nj][2] * scale, v3 = s[nj][3] * scale;
                if (c0 > row1)     v0 = -1e30f;
                if (c0 + 1 > row1) v1 = -1e30f;
                if (c0 > row2)     v2 = -1e30f;
                if (c0 + 1 > row2) v3 = -1e30f;
                s[nj][0] = v0; s[nj][1] = v1; s[nj][2] = v2; s[nj][3] = v3;
                rmax1 = fmaxf(rmax1, fmaxf(v0, v1));
                rmax2 = fmaxf(rmax2, fmaxf(v2, v3));
            }
#pragma unroll
            for (int off = 1; off <= 2; off <<= 1) {
                rmax1 = fmaxf(rmax1, __shfl_xor_sync(0xffffffffu, rmax1, off));
                rmax2 = fmaxf(rmax2, __shfl_xor_sync(0xffffffffu, rmax2, off));
            }
            const float mn1 = fmaxf(m1, rmax1);
            const float mn2 = fmaxf(m2, rmax2);
            const float al1 = expf(m1 - mn1);
            const float al2 = expf(m2 - mn2);
            m1 = mn1; m2 = mn2;

            float ps1 = 0.f, ps2 = 0.f;
#pragma unroll
            for (int nj = 0; nj < 8; nj++) {
                float p0 = expf(s[nj][0] - mn1);
                float p1 = expf(s[nj][1] - mn1);
                float p2 = expf(s[nj][2] - mn2);
                float p3 = expf(s[nj][3] - mn2);
                s[nj][0] = p0; s[nj][1] = p1; s[nj][2] = p2; s[nj][3] = p3;
                ps1 += p0 + p1;
                ps2 += p2 + p3;
            }
#pragma unroll
            for (int off = 1; off <= 2; off <<= 1) {
                ps1 += __shfl_xor_sync(0xffffffffu, ps1, off);
                ps2 += __shfl_xor_sync(0xffffffffu, ps2, off);
            }
            l1 = l1 * al1 + ps1;
            l2 = l2 * al2 + ps2;
#pragma unroll
            for (int nj = 0; nj < 16; nj++) {
                accO[nj][0] *= al1; accO[nj][1] *= al1;
                accO[nj][2] *= al2; accO[nj][3] *= al2;
            }

            // ---- O += P V ----
            const uint32_t vbuf = kbuf + 16384;
#pragma unroll
            for (int kv = 0; kv < 4; kv++) {
                const uint32_t a0 = packh2(s[2 * kv][0],     s[2 * kv][1]);
                const uint32_t a1 = packh2(s[2 * kv][2],     s[2 * kv][3]);
                const uint32_t a2 = packh2(s[2 * kv + 1][0], s[2 * kv + 1][1]);
                const uint32_t a3 = packh2(s[2 * kv + 1][2], s[2 * kv + 1][3]);
#pragma unroll
                for (int p = 0; p < 8; p++) {
                    const int seg = p >> 2;
                    const uint32_t ro = (uint32_t)((kv * 16 + rV) * 128);
                    uint32_t b0, b1, b2, b3;
                    ldsm4t(b0, b1, b2, b3,
                           vbuf + seg * 8192 + ro
                           + (((uint32_t)((p & 3) * 32 + dbV)) ^ ((ro >> 3) & 0x70)));
                    mma_f16(accO[2 * p],     a0, a1, a2, a3, b0, b1);
                    mma_f16(accO[2 * p + 1], a0, a1, a2, a3, b2, b3);
                }
            }
        }
        __syncthreads();
    }
#undef LOADKV

    // ---- epilogue ----
    const float inv1 = 1.f / l1;
    const float inv2 = 1.f / l2;
    const int row1 = qr0 + (lane >> 2);
    const int colb = head * D_ + (lane & 3) * 2;
#pragma unroll
    for (int nj = 0; nj < 16; nj++) {
        __half2* d1 = (__half2*)(o + (size_t)row1 * H_ + colb + nj * 8);
        __half2* d2 = (__half2*)(o + (size_t)(row1 + 8) * H_ + colb + nj * 8);
        *d1 = __floats2half2_rn(accO[nj][0] * inv1, accO[nj][1] * inv1);
        *d2 = __floats2half2_rn(accO[nj][2] * inv2, accO[nj][3] * inv2);
    }
}

// ---------------- launch ----------------
static inline void conv_w(const float* src, __half* dst, size_t n) {
    int n4 = (int)(n / 4);
    f2h_kernel<<<(n4 + 255) / 256, 256>>>((const float4*)src, (__half2*)dst, n4);
}

extern "C" void kernel_launch(void* const* d_in, const int* in_sizes, int n_in,
                              void* d_out, int out_size)
{
    (void)in_sizes; (void)n_in; (void)out_size;
    const float* x      = (const float*)d_in[0];
    const int*   pos    = (const int*)  d_in[1];
    const float* w_q    = (const float*)d_in[2];
    const float* w_k    = (const float*)d_in[3];
    const float* w_v    = (const float*)d_in[4];
    const float* w_o    = (const float*)d_in[5];
    const float* w_gate = (const float*)d_in[6];
    const float* w_up   = (const float*)d_in[7];
    const float* w_down = (const float*)d_in[8];
    const float* rms1   = (const float*)d_in[9];
    const float* rms2   = (const float*)d_in[10];
    float* out = (float*)d_out;

    __half *h, *attn, *gu, *qh, *kh, *vh, *wq, *wk, *wv, *wo, *wg, *wu, *wd;
    float *q, *k, *x1, *gate;
    cudaGetSymbolAddress((void**)&h,    g_h);
    cudaGetSymbolAddress((void**)&q,    g_q);
    cudaGetSymbolAddress((void**)&k,    g_k);
    cudaGetSymbolAddress((void**)&qh,   g_qh);
    cudaGetSymbolAddress((void**)&kh,   g_kh);
    cudaGetSymbolAddress((void**)&vh,   g_vh);
    cudaGetSymbolAddress((void**)&attn, g_attn);
    cudaGetSymbolAddress((void**)&x1,   g_x1);
    cudaGetSymbolAddress((void**)&gate, g_gate);
    cudaGetSymbolAddress((void**)&gu,   g_gu);
    cudaGetSymbolAddress((void**)&wq,   g_wq);
    cudaGetSymbolAddress((void**)&wk,   g_wk);
    cudaGetSymbolAddress((void**)&wv,   g_wv);
    cudaGetSymbolAddress((void**)&wo,   g_wo);
    cudaGetSymbolAddress((void**)&wg,   g_wg);
    cudaGetSymbolAddress((void**)&wu,   g_wu);
    cudaGetSymbolAddress((void**)&wd,   g_wd);

    cudaFuncSetAttribute(attn16_kernel, cudaFuncAttributeMaxDynamicSharedMemorySize, ATT_SMEM);
    cudaFuncSetAttribute(gemm_f16_kernel<0,0>, cudaFuncAttributeMaxDynamicSharedMemorySize, GEMM_SMEM);
    cudaFuncSetAttribute(gemm_f16_kernel<0,1>, cudaFuncAttributeMaxDynamicSharedMemorySize, GEMM_SMEM);
    cudaFuncSetAttribute(gemm_f16_kernel<1,0>, cudaFuncAttributeMaxDynamicSharedMemorySize, GEMM_SMEM);
    cudaFuncSetAttribute(gemm_f16_kernel<2,0>, cudaFuncAttributeMaxDynamicSharedMemorySize, GEMM_SMEM);
    cudaFuncSetAttribute(gemm_f16_kernel<3,1>, cudaFuncAttributeMaxDynamicSharedMemorySize, GEMM_SMEM);

    // 0. weights -> fp16
    conv_w(w_q,    wq, (size_t)H_ * H_);
    conv_w(w_k,    wk, (size_t)(HKV_ * D_) * H_);
    conv_w(w_v,    wv, (size_t)(HKV_ * D_) * H_);
    conv_w(w_o,    wo, (size_t)H_ * H_);
    conv_w(w_gate, wg, (size_t)I_ * H_);
    conv_w(w_up,   wu, (size_t)I_ * H_);
    conv_w(w_down, wd, (size_t)H_ * I_);

    // 1. h = rmsnorm(x) * rms1  (fp16)
    rmsnorm_kernel<<<T_, 256>>>(x, rms1, h);
    // 2. q/k/v projections
    gemm_f16_kernel<0,0><<<dim3(H_ / 128, T_ / 128), 256, GEMM_SMEM>>>(h, wq, nullptr, q, H_, H_);
    gemm_f16_kernel<0,0><<<dim3((HKV_ * D_) / 128, T_ / 128), 256, GEMM_SMEM>>>(h, wk, nullptr, k, HKV_ * D_, H_);
    gemm_f16_kernel<0,1><<<dim3((HKV_ * D_) / 128, T_ / 128), 256, GEMM_SMEM>>>(h, wv, nullptr, vh, HKV_ * D_, H_);
    // 3. RoPE (fp32 -> fp16)
    rope_kernel<<<dim3(T_, HQ_), 64>>>(q, pos, qh, HQ_);
    rope_kernel<<<dim3(T_, HKV_), 64>>>(k, pos, kh, HKV_);
    // 4. causal attention (fp16 tensor cores)
    attn16_kernel<<<dim3(T_ / 128, HQ_), 256, ATT_SMEM>>>(qh, kh, vh, attn);
    // 5. x1 = x + attn @ w_o^T
    gemm_f16_kernel<1,0><<<dim3(H_ / 128, T_ / 128), 256, GEMM_SMEM>>>(attn, wo, x, x1, H_, H_);
    // 6. h = rmsnorm(x1) * rms2 (fp16)
    rmsnorm_kernel<<<T_, 256>>>(x1, rms2, h);
    // 7. gate = silu(h @ w_gate^T)  (fp32)
    gemm_f16_kernel<2,0><<<dim3(I_ / 128, T_ / 128), 256, GEMM_SMEM>>>(h, wg, nullptr, gate, I_, H_);
    // 8. gu = gate * (h @ w_up^T)  (fp16)
    gemm_f16_kernel<3,1><<<dim3(I_ / 128, T_ / 128), 256, GEMM_SMEM>>>(h, wu, gate, gu, I_, H_);
    // 9. out = x1 + gu @ w_down^T
    gemm_f16_kernel<1,0><<<dim3(H_ / 128, T_ / 128), 256, GEMM_SMEM>>>(gu, wd, x1, out, H_, I_);
}